// round 7
// baseline (speedup 1.0000x reference)
#include <cuda_runtime.h>
#include <cuda_fp16.h>
#include <cstdint>
#include <cstddef>

// Problem dims: y[b,m,n] = sum_k x[b,m,k] w[k,n]; flatten b,m -> M
#define MDIM 8192
#define KDIM 4096
#define NDIM 4096
#define KB16 (KDIM / 16)  // 256 k-blocks of 16

// GEMM tiling: CTA 128x128x64, 8 warps (2m x 4n), warp tile 64x32, 4 stages
// A fp16 in smem; W int8 (permuted, +1 biased) in smem -> in-reg expand to fp16
#define BM 128
#define BN 128
#define BK 64
#define STAGES 4
#define KT (KDIM / BK)  // 64
#define THREADS 256

#define LDA 72                          // 64 + 8 pad (fp16 elems per A smem row)
#define A_TILE_B (BM * LDA * 2)         // 18432
#define B_TILE_B (4 * BN * 16)          // 8192: rows = kbl*128 + n, 16B each
#define STAGE_B (A_TILE_B + B_TILE_B)   // 26624
#define SMEM_B (STAGES * STAGE_B)       // 106496 -> 2 CTAs/SM

// scratch (allocation-free rule: __device__ globals)
__device__ __half g_xh[(size_t)MDIM * KDIM];          // 67 MB fp16 x
__device__ uint4 g_w8[(size_t)NDIM * KB16];           // 16.8 MB permuted int8 w+1

static __device__ __forceinline__ uint32_t smem_u32(const void* p) {
    uint32_t a;
    asm("{ .reg .u64 t; cvta.to.shared.u64 t, %1; cvt.u32.u64 %0, t; }"
        : "=r"(a) : "l"(p));
    return a;
}

#define CP_ASYNC16(dst, src) \
    asm volatile("cp.async.cg.shared.global [%0], [%1], 16;" :: "r"(dst), "l"(src))
#define CP_COMMIT() asm volatile("cp.async.commit_group;" ::: "memory")
#define CP_WAIT(n)  asm volatile("cp.async.wait_group %0;" :: "n"(n) : "memory")

#define LDMATRIX_X4(r0, r1, r2, r3, addr)                                  \
    asm volatile("ldmatrix.sync.aligned.m8n8.x4.shared.b16 "               \
                 "{%0,%1,%2,%3}, [%4];"                                    \
                 : "=r"(r0), "=r"(r1), "=r"(r2), "=r"(r3) : "r"(addr))

#define MMA16816(d, a, b0, b1)                                             \
    asm volatile("mma.sync.aligned.m16n8k16.row.col.f32.f16.f16.f32 "      \
                 "{%0,%1,%2,%3}, {%4,%5,%6,%7}, {%8,%9}, {%0,%1,%2,%3};"   \
                 : "+f"((d)[0]), "+f"((d)[1]), "+f"((d)[2]), "+f"((d)[3])  \
                 : "r"((a)[0]), "r"((a)[1]), "r"((a)[2]), "r"((a)[3]),     \
                   "r"(b0), "r"(b1))

// int8(w+1) -> two fp16x2 frag regs. (0x6400|b) = 1024+b exactly; -1025 -> w.
static __device__ __forceinline__ void expand_b(uint32_t v, uint32_t& b0,
                                                uint32_t& b1) {
    const uint32_t MAG = 0x64646464u, BIAS = 0x64016401u;
    uint32_t lo, hi;
    asm("prmt.b32 %0, %1, %2, 0x4140;" : "=r"(lo) : "r"(v), "r"(MAG));
    asm("prmt.b32 %0, %1, %2, 0x4342;" : "=r"(hi) : "r"(v), "r"(MAG));
    asm("sub.f16x2 %0, %1, %2;" : "=r"(b0) : "r"(lo), "r"(BIAS));
    asm("sub.f16x2 %0, %1, %2;" : "=r"(b1) : "r"(hi), "r"(BIAS));
}

// ---------------------------------------------------------------------------
// prep: x -> fp16; w -> permuted int8(+1), layout g_w8[n*KB16 + kb] (16B).
// Byte 4j+{0,1,2,3} of block (n,kb) = w[16kb + {2j, 2j+1, 2j+8, 2j+9}][n] + 1,
// so ldmatrix.x4.b16 delivers mma-B-fragment bytes directly.
// ---------------------------------------------------------------------------
#define XCHUNKS ((size_t)MDIM * KDIM / 4)   // 8388608 float4s (x part)
#define WTHREADS ((size_t)NDIM * KB16)      // 1048576 (w part)

__global__ void cvt_kernel(const float4* __restrict__ x4,
                           const float* __restrict__ w) {
    size_t idx = (size_t)blockIdx.x * blockDim.x + threadIdx.x;
    if (idx < XCHUNKS) {
        float4 v = x4[idx];
        __half2 h0 = __floats2half2_rn(v.x, v.y);
        __half2 h1 = __floats2half2_rn(v.z, v.w);
        uint2 o;
        o.x = *reinterpret_cast<uint32_t*>(&h0);
        o.y = *reinterpret_cast<uint32_t*>(&h1);
        reinterpret_cast<uint2*>(g_xh)[idx] = o;
    } else {
        size_t wi = idx - XCHUNKS;
        int n = (int)(wi & (NDIM - 1));   // consecutive lanes -> consecutive n
        int kb = (int)(wi >> 12);
        const float* col = w + (size_t)(kb * 16) * NDIM + n;
        uint32_t q[4];
#pragma unroll
        for (int j = 0; j < 4; ++j) {
            uint32_t b0 = (uint32_t)(int)(col[(size_t)(2 * j) * NDIM] + 1.0f);
            uint32_t b1 = (uint32_t)(int)(col[(size_t)(2 * j + 1) * NDIM] + 1.0f);
            uint32_t b2 = (uint32_t)(int)(col[(size_t)(2 * j + 8) * NDIM] + 1.0f);
            uint32_t b3 = (uint32_t)(int)(col[(size_t)(2 * j + 9) * NDIM] + 1.0f);
            q[j] = b0 | (b1 << 8) | (b2 << 16) | (b3 << 24);
        }
        g_w8[(size_t)n * KB16 + kb] = make_uint4(q[0], q[1], q[2], q[3]);
    }
}

// ---------------------------------------------------------------------------
// GEMM
// ---------------------------------------------------------------------------
__global__ void __launch_bounds__(THREADS, 2) gemm_kernel(float* __restrict__ out) {
    extern __shared__ char smem_raw[];
    const uint32_t smem = smem_u32(smem_raw);

    const int tid = threadIdx.x;
    const int lane = tid & 31;
    const int wid = tid >> 5;
    const int warp_m = wid & 1;   // 0..1
    const int warp_n = wid >> 1;  // 0..3

    const int m0 = blockIdx.y * BM;
    const int n0 = blockIdx.x * BN;

    const __half* gA = g_xh + (size_t)m0 * KDIM;

    // ---- A cp.async: 1024 chunks of 16B, 4/thread ----
    uint32_t sA_dst[4];
    const __half* gA_src[4];
#pragma unroll
    for (int i = 0; i < 4; ++i) {
        int c = tid + i * THREADS;
        int row = c >> 3, ch = c & 7;
        sA_dst[i] = smem + (uint32_t)(row * LDA + ch * 8) * 2;
        gA_src[i] = gA + (size_t)row * KDIM + ch * 8;
    }
    // ---- B cp.async: 512 chunks of 16B, 2/thread; chunk c -> smem row c ----
    // c = kbl*128 + n ; thread handles c = tid (kbl = tid>>7) and c = tid+256
    const int bn = tid & 127;
    const int bkbl = tid >> 7;  // 0 or 1; second chunk is kbl+2
    const uint8_t* gB_base =
        reinterpret_cast<const uint8_t*>(g_w8) +
        ((size_t)(n0 + bn) * KB16 + bkbl) * 16;
    const uint32_t sB_dst0 = smem + A_TILE_B + (uint32_t)tid * 16;

#define ISSUE_STAGE(slot, kt_)                                              \
    do {                                                                    \
        const uint32_t sb = (uint32_t)(slot) * STAGE_B;                     \
        const size_t kb = (size_t)(kt_) * BK;                               \
        _Pragma("unroll")                                                   \
        for (int i = 0; i < 4; ++i)                                         \
            CP_ASYNC16(sA_dst[i] + sb, gA_src[i] + kb);                     \
        CP_ASYNC16(sB_dst0 + sb, gB_base + (size_t)(kt_) * 64);             \
        CP_ASYNC16(sB_dst0 + sb + 4096, gB_base + (size_t)(kt_) * 64 + 32); \
    } while (0)

    // ---- fragment base addresses ----
    const uint32_t a_frag =
        smem + (uint32_t)((warp_m * 64 + (lane & 15)) * LDA + (lane >> 4) * 8) * 2;
    // B: lane l supplies row (kk*128 + warp_n*32 + l) of 16B
    const uint32_t b_frag =
        smem + A_TILE_B + (uint32_t)(warp_n * 32 + lane) * 16;

    float acc[4][4][4];
#pragma unroll
    for (int mi = 0; mi < 4; ++mi)
#pragma unroll
        for (int ni = 0; ni < 4; ++ni)
#pragma unroll
            for (int q = 0; q < 4; ++q) acc[mi][ni][q] = 0.f;

    // ---- prologue ----
#pragma unroll
    for (int s = 0; s < STAGES - 1; ++s) {
        ISSUE_STAGE(s, s);
        CP_COMMIT();
    }

    // ---- mainloop ----
    int s_cur = 0;
    int s_nxt = STAGES - 1;
    for (int kt = 0; kt < KT; ++kt) {
        CP_WAIT(STAGES - 2);
        __syncthreads();

        if (kt + STAGES - 1 < KT) ISSUE_STAGE(s_nxt, kt + STAGES - 1);
        CP_COMMIT();

        const uint32_t sb = (uint32_t)s_cur * STAGE_B;
        const uint32_t aB = a_frag + sb;
        const uint32_t bB = b_frag + sb;

#pragma unroll
        for (int kk = 0; kk < 4; ++kk) {
            uint32_t a[4][4], braw[4];
#pragma unroll
            for (int mi = 0; mi < 4; ++mi)
                LDMATRIX_X4(a[mi][0], a[mi][1], a[mi][2], a[mi][3],
                            aB + (uint32_t)(mi * 16 * LDA + kk * 16) * 2);
            LDMATRIX_X4(braw[0], braw[1], braw[2], braw[3],
                        bB + (uint32_t)(kk * 128) * 16);
#pragma unroll
            for (int nj = 0; nj < 4; ++nj) {
                uint32_t b0, b1;
                expand_b(braw[nj], b0, b1);
#pragma unroll
                for (int mi = 0; mi < 4; ++mi)
                    MMA16816(acc[mi][nj], a[mi], b0, b1);
            }
        }
        if (++s_cur == STAGES) s_cur = 0;
        if (++s_nxt == STAGES) s_nxt = 0;
    }

    // ---- epilogue: direct fp32 stores ----
    const int mg = m0 + warp_m * 64 + (lane >> 2);
    const int ng = n0 + warp_n * 32 + (lane & 3) * 2;
#pragma unroll
    for (int mi = 0; mi < 4; ++mi) {
#pragma unroll
        for (int ni = 0; ni < 4; ++ni) {
            float* p0 = out + (size_t)(mg + mi * 16) * NDIM + ng + ni * 8;
            float* p1 = p0 + 8 * NDIM;
            *reinterpret_cast<float2*>(p0) = make_float2(acc[mi][ni][0], acc[mi][ni][1]);
            *reinterpret_cast<float2*>(p1) = make_float2(acc[mi][ni][2], acc[mi][ni][3]);
        }
    }
}

// ---------------------------------------------------------------------------
extern "C" void kernel_launch(void* const* d_in, const int* in_sizes, int n_in,
                              void* d_out, int out_size) {
    const float* x = (const float*)d_in[0];  // (4, 2048, 4096) fp32
    const float* w = (const float*)d_in[1];  // (4096, 4096) fp32 ternary
    float* out = (float*)d_out;              // (4, 2048, 4096) fp32

    size_t total = XCHUNKS + WTHREADS;  // 9437184
    cvt_kernel<<<(int)(total / 256), 256>>>(
        reinterpret_cast<const float4*>(x), w);

    cudaFuncSetAttribute(gemm_kernel, cudaFuncAttributeMaxDynamicSharedMemorySize,
                         SMEM_B);
    dim3 grid(NDIM / BN, MDIM / BM);  // (32, 64)
    gemm_kernel<<<grid, THREADS, SMEM_B>>>(out);
}

// round 8
// speedup vs baseline: 1.0146x; 1.0146x over previous
#include <cuda_runtime.h>
#include <cuda_fp16.h>
#include <cstdint>
#include <cstddef>

// Problem dims: y[b,m,n] = sum_k x[b,m,k] w[k,n]; flatten b,m -> M
#define MDIM 8192
#define KDIM 4096
#define NDIM 4096
#define KB16 (KDIM / 16)  // 256 k-blocks of 16

// GEMM tiling: CTA 128x128x64, 8 warps (2m x 4n), warp tile 64x32, 4 stages
// A fp16 in smem; W int8 (permuted, +1 biased) in smem -> in-reg expand to fp16
#define BM 128
#define BN 128
#define BK 64
#define STAGES 4
#define KT (KDIM / BK)  // 64
#define THREADS 256

#define LDA 72                          // 64 + 8 pad (fp16 elems per A smem row)
#define A_TILE_B (BM * LDA * 2)         // 18432
#define B_TILE_B (4 * BN * 16)          // 8192: rows = kbl*128 + n, 16B each
#define STAGE_B (A_TILE_B + B_TILE_B)   // 26624
#define SMEM_B (STAGES * STAGE_B)       // 106496 -> 2 CTAs/SM

// scratch (allocation-free rule: __device__ globals)
__device__ __half g_xh[(size_t)MDIM * KDIM];          // 67 MB fp16 x
__device__ uint4 g_w8[(size_t)NDIM * KB16];           // 16.8 MB permuted int8 w+1

static __device__ __forceinline__ uint32_t smem_u32(const void* p) {
    uint32_t a;
    asm("{ .reg .u64 t; cvta.to.shared.u64 t, %1; cvt.u32.u64 %0, t; }"
        : "=r"(a) : "l"(p));
    return a;
}

#define CP_ASYNC16(dst, src) \
    asm volatile("cp.async.cg.shared.global [%0], [%1], 16;" :: "r"(dst), "l"(src))
#define CP_COMMIT() asm volatile("cp.async.commit_group;" ::: "memory")
#define CP_WAIT(n)  asm volatile("cp.async.wait_group %0;" :: "n"(n) : "memory")

#define LDMATRIX_X4(r0, r1, r2, r3, addr)                                  \
    asm volatile("ldmatrix.sync.aligned.m8n8.x4.shared.b16 "               \
                 "{%0,%1,%2,%3}, [%4];"                                    \
                 : "=r"(r0), "=r"(r1), "=r"(r2), "=r"(r3) : "r"(addr))

#define MMA16816(d, a, b0, b1)                                             \
    asm volatile("mma.sync.aligned.m16n8k16.row.col.f32.f16.f16.f32 "      \
                 "{%0,%1,%2,%3}, {%4,%5,%6,%7}, {%8,%9}, {%0,%1,%2,%3};"   \
                 : "+f"((d)[0]), "+f"((d)[1]), "+f"((d)[2]), "+f"((d)[3])  \
                 : "r"((a)[0]), "r"((a)[1]), "r"((a)[2]), "r"((a)[3]),     \
                   "r"(b0), "r"(b1))

// ---------------------------------------------------------------------------
// prep: x -> fp16; w -> permuted int8(+1), layout g_w8[n*KB16 + kb] (16B).
// Byte 4j+{0,1,2,3} of block (n,kb) = w[16kb + {2j, 2j+1, 2j+8, 2j+9}][n] + 1,
// so ldmatrix.x4.b16 delivers mma-B-fragment bytes directly.
// ---------------------------------------------------------------------------
#define XCHUNKS ((size_t)MDIM * KDIM / 4)   // 8388608 float4s (x part)
#define WTHREADS ((size_t)NDIM * KB16)      // 1048576 (w part)

__global__ void cvt_kernel(const float4* __restrict__ x4,
                           const float* __restrict__ w) {
    size_t idx = (size_t)blockIdx.x * blockDim.x + threadIdx.x;
    if (idx < XCHUNKS) {
        float4 v = x4[idx];
        __half2 h0 = __floats2half2_rn(v.x, v.y);
        __half2 h1 = __floats2half2_rn(v.z, v.w);
        uint2 o;
        o.x = *reinterpret_cast<uint32_t*>(&h0);
        o.y = *reinterpret_cast<uint32_t*>(&h1);
        reinterpret_cast<uint2*>(g_xh)[idx] = o;
    } else {
        size_t wi = idx - XCHUNKS;
        int n = (int)(wi & (NDIM - 1));   // consecutive lanes -> consecutive n
        int kb = (int)(wi >> 12);
        const float* col = w + (size_t)(kb * 16) * NDIM + n;
        uint32_t q[4];
#pragma unroll
        for (int j = 0; j < 4; ++j) {
            uint32_t b0 = (uint32_t)(int)(col[(size_t)(2 * j) * NDIM] + 1.0f);
            uint32_t b1 = (uint32_t)(int)(col[(size_t)(2 * j + 1) * NDIM] + 1.0f);
            uint32_t b2 = (uint32_t)(int)(col[(size_t)(2 * j + 8) * NDIM] + 1.0f);
            uint32_t b3 = (uint32_t)(int)(col[(size_t)(2 * j + 9) * NDIM] + 1.0f);
            q[j] = b0 | (b1 << 8) | (b2 << 16) | (b3 << 24);
        }
        g_w8[(size_t)n * KB16 + kb] = make_uint4(q[0], q[1], q[2], q[3]);
    }
}

// ---------------------------------------------------------------------------
// GEMM: B-first LDSM order, B pipelined one kk ahead, batched expansion
// ---------------------------------------------------------------------------
__global__ void __launch_bounds__(THREADS, 2) gemm_kernel(float* __restrict__ out) {
    extern __shared__ char smem_raw[];
    const uint32_t smem = smem_u32(smem_raw);

    const int tid = threadIdx.x;
    const int lane = tid & 31;
    const int wid = tid >> 5;
    const int warp_m = wid & 1;   // 0..1
    const int warp_n = wid >> 1;  // 0..3

    const int m0 = blockIdx.y * BM;
    const int n0 = blockIdx.x * BN;

    const __half* gA = g_xh + (size_t)m0 * KDIM;

    // ---- A cp.async: 1024 chunks of 16B, 4/thread ----
    uint32_t sA_dst[4];
    const __half* gA_src[4];
#pragma unroll
    for (int i = 0; i < 4; ++i) {
        int c = tid + i * THREADS;
        int row = c >> 3, ch = c & 7;
        sA_dst[i] = smem + (uint32_t)(row * LDA + ch * 8) * 2;
        gA_src[i] = gA + (size_t)row * KDIM + ch * 8;
    }
    // ---- B cp.async: 512 chunks of 16B, 2/thread; chunk c -> smem row c ----
    const int bn = tid & 127;
    const int bkbl = tid >> 7;  // 0 or 1; second chunk is kbl+2
    const uint8_t* gB_base =
        reinterpret_cast<const uint8_t*>(g_w8) +
        ((size_t)(n0 + bn) * KB16 + bkbl) * 16;
    const uint32_t sB_dst0 = smem + A_TILE_B + (uint32_t)tid * 16;

#define ISSUE_STAGE(slot, kt_)                                              \
    do {                                                                    \
        const uint32_t sb = (uint32_t)(slot) * STAGE_B;                     \
        const size_t kb = (size_t)(kt_) * BK;                               \
        _Pragma("unroll")                                                   \
        for (int i = 0; i < 4; ++i)                                         \
            CP_ASYNC16(sA_dst[i] + sb, gA_src[i] + kb);                     \
        CP_ASYNC16(sB_dst0 + sb, gB_base + (size_t)(kt_) * 64);             \
        CP_ASYNC16(sB_dst0 + sb + 4096, gB_base + (size_t)(kt_) * 64 + 32); \
    } while (0)

    // ---- fragment base addresses ----
    const uint32_t a_frag =
        smem + (uint32_t)((warp_m * 64 + (lane & 15)) * LDA + (lane >> 4) * 8) * 2;
    // B: lane l supplies row (kk*128 + warp_n*32 + l) of 16B
    const uint32_t b_frag =
        smem + A_TILE_B + (uint32_t)(warp_n * 32 + lane) * 16;

    float acc[4][4][4];
#pragma unroll
    for (int mi = 0; mi < 4; ++mi)
#pragma unroll
        for (int ni = 0; ni < 4; ++ni)
#pragma unroll
            for (int q = 0; q < 4; ++q) acc[mi][ni][q] = 0.f;

    // ---- prologue ----
#pragma unroll
    for (int s = 0; s < STAGES - 1; ++s) {
        ISSUE_STAGE(s, s);
        CP_COMMIT();
    }

    // ---- mainloop ----
    int s_cur = 0;
    int s_nxt = STAGES - 1;
    for (int kt = 0; kt < KT; ++kt) {
        CP_WAIT(STAGES - 2);
        __syncthreads();

        if (kt + STAGES - 1 < KT) ISSUE_STAGE(s_nxt, kt + STAGES - 1);
        CP_COMMIT();

        const uint32_t sb = (uint32_t)s_cur * STAGE_B;
        const uint32_t aB = a_frag + sb;
        const uint32_t bB = b_frag + sb;

        // B for kk=0 first: its latency hides under the A LDSMs below
        uint32_t braw[4];
        LDMATRIX_X4(braw[0], braw[1], braw[2], braw[3], bB);

#pragma unroll
        for (int kk = 0; kk < 4; ++kk) {
            uint32_t a[4][4];
#pragma unroll
            for (int mi = 0; mi < 4; ++mi)
                LDMATRIX_X4(a[mi][0], a[mi][1], a[mi][2], a[mi][3],
                            aB + (uint32_t)(mi * 16 * LDA + kk * 16) * 2);

            // pipeline next kk's B before consuming this kk's
            uint32_t bnext[4];
            if (kk < 3)
                LDMATRIX_X4(bnext[0], bnext[1], bnext[2], bnext[3],
                            bB + (uint32_t)((kk + 1) * 128) * 16);

            // batched expansion: 8 independent prmt, then 8 independent sub
            const uint32_t MAG = 0x64646464u, BIAS = 0x64016401u;
            uint32_t lo[4], hi[4], b0[4], b1[4];
#pragma unroll
            for (int nj = 0; nj < 4; ++nj) {
                asm("prmt.b32 %0, %1, %2, 0x4140;" : "=r"(lo[nj]) : "r"(braw[nj]), "r"(MAG));
                asm("prmt.b32 %0, %1, %2, 0x4342;" : "=r"(hi[nj]) : "r"(braw[nj]), "r"(MAG));
            }
#pragma unroll
            for (int nj = 0; nj < 4; ++nj) {
                asm("sub.f16x2 %0, %1, %2;" : "=r"(b0[nj]) : "r"(lo[nj]), "r"(BIAS));
                asm("sub.f16x2 %0, %1, %2;" : "=r"(b1[nj]) : "r"(hi[nj]), "r"(BIAS));
            }

#pragma unroll
            for (int nj = 0; nj < 4; ++nj)
#pragma unroll
                for (int mi = 0; mi < 4; ++mi)
                    MMA16816(acc[mi][nj], a[mi], b0[nj], b1[nj]);

#pragma unroll
            for (int nj = 0; nj < 4; ++nj) braw[nj] = bnext[nj];
        }
        if (++s_cur == STAGES) s_cur = 0;
        if (++s_nxt == STAGES) s_nxt = 0;
    }

    // ---- epilogue: direct fp32 stores ----
    const int mg = m0 + warp_m * 64 + (lane >> 2);
    const int ng = n0 + warp_n * 32 + (lane & 3) * 2;
#pragma unroll
    for (int mi = 0; mi < 4; ++mi) {
#pragma unroll
        for (int ni = 0; ni < 4; ++ni) {
            float* p0 = out + (size_t)(mg + mi * 16) * NDIM + ng + ni * 8;
            float* p1 = p0 + 8 * NDIM;
            *reinterpret_cast<float2*>(p0) = make_float2(acc[mi][ni][0], acc[mi][ni][1]);
            *reinterpret_cast<float2*>(p1) = make_float2(acc[mi][ni][2], acc[mi][ni][3]);
        }
    }
}

// ---------------------------------------------------------------------------
extern "C" void kernel_launch(void* const* d_in, const int* in_sizes, int n_in,
                              void* d_out, int out_size) {
    const float* x = (const float*)d_in[0];  // (4, 2048, 4096) fp32
    const float* w = (const float*)d_in[1];  // (4096, 4096) fp32 ternary
    float* out = (float*)d_out;              // (4, 2048, 4096) fp32

    size_t total = XCHUNKS + WTHREADS;  // 9437184
    cvt_kernel<<<(int)(total / 256), 256>>>(
        reinterpret_cast<const float4*>(x), w);

    cudaFuncSetAttribute(gemm_kernel, cudaFuncAttributeMaxDynamicSharedMemorySize,
                         SMEM_B);
    dim3 grid(NDIM / BN, MDIM / BM);  // (32, 64)
    gemm_kernel<<<grid, THREADS, SMEM_B>>>(out);
}